// round 5
// baseline (speedup 1.0000x reference)
#include <cuda_runtime.h>
#include <math.h>
#include <cstdint>

// Problem constants
#define NB    16
#define NPTS  4096
#define MPTS  1024
#define CH2   256
#define CH1   128
#define OUT1  256
#define OUT2  256
#define LDA_W1 384

// ---- scratch ----
__device__ int   g_idx[NB * NPTS * 3];
__device__ float g_wgt[NB * NPTS * 3];
__device__ float g_Tt [NB * MPTS * OUT1];   // T transposed: [b][m][o], o contiguous
__device__ float g_y1 [NB * OUT1 * NPTS];   // layer-1 activations [b][k][n]

// ===========================================================================
// Kernel 1: three_nn + weights
// ===========================================================================
__global__ __launch_bounds__(256)
void three_nn_kernel(const float* __restrict__ xyz1, const float* __restrict__ xyz2)
{
    __shared__ float sx[MPTS], sy[MPTS], sz[MPTS], ss[MPTS];
    const int b = blockIdx.y;
    const float* x2 = xyz2 + (size_t)b * 3 * MPTS;
    for (int i = threadIdx.x; i < MPTS; i += blockDim.x) {
        float xv = x2[i], yv = x2[MPTS + i], zv = x2[2 * MPTS + i];
        sx[i] = xv; sy[i] = yv; sz[i] = zv;
        ss[i] = xv * xv + yv * yv + zv * zv;
    }
    __syncthreads();

    const int n = blockIdx.x * blockDim.x + threadIdx.x;
    const float* x1 = xyz1 + (size_t)b * 3 * NPTS;
    const float px = x1[n], py = x1[NPTS + n], pz = x1[2 * NPTS + n];
    const float sq1 = px * px + py * py + pz * pz;

    float d0 = 1e30f, d1 = 1e30f, d2 = 1e30f;
    int   i0 = 0, i1 = 0, i2 = 0;

    #pragma unroll 4
    for (int m = 0; m < MPTS; m++) {
        float inner = fmaf(px, sx[m], fmaf(py, sy[m], pz * sz[m]));
        float d = fmaf(-2.0f, inner, sq1 + ss[m]);
        if (d < d2) {
            if (d < d1) {
                d2 = d1; i2 = i1;
                if (d < d0) { d1 = d0; i1 = i0; d0 = d; i0 = m; }
                else        { d1 = d;  i1 = m; }
            } else { d2 = d; i2 = m; }
        }
    }

    float r0 = 1.0f / fmaxf(sqrtf(fmaxf(d0, 1e-20f)), 1e-10f);
    float r1 = 1.0f / fmaxf(sqrtf(fmaxf(d1, 1e-20f)), 1e-10f);
    float r2 = 1.0f / fmaxf(sqrtf(fmaxf(d2, 1e-20f)), 1e-10f);
    float inv = 1.0f / (r0 + r1 + r2);

    const int base = (b * NPTS + n) * 3;
    g_idx[base + 0] = i0; g_idx[base + 1] = i1; g_idx[base + 2] = i2;
    g_wgt[base + 0] = r0 * inv; g_wgt[base + 1] = r1 * inv; g_wgt[base + 2] = r2 * inv;
}

// ===========================================================================
// tf32 mma.sync GEMM, CTA tile 128x256, warp tile 64x64, BK=8 double-buffered.
//   MODE 0: Tt  = (W1[:, :256] @ points2)^T                 -> g_Tt [m][o]
//   MODE 1: y1  = relu(W1[:,256:] @ points1 + b1 + gather)  -> g_y1
//   MODE 2: out = relu(W2 @ y1 + b2)                        -> d_out
// 8 warps (2x4), mma.m16n8k8.tf32.
// ===========================================================================
__device__ __forceinline__ uint32_t f2tf32(float x) {
    uint32_t r;
    asm("cvt.rna.tf32.f32 %0, %1;" : "=r"(r) : "f"(x));
    return r;
}

#define BK     8
#define BN     256
#define ASTR   20    // frag bank = (20g+tc)%32 bijective; STS wavefront conflict-free
#define BSTR   264   // (256+8): frag bank = (8tc+g)%32 bijective

template <int MODE>
__global__ __launch_bounds__(256)
void gemm_mma(const float* __restrict__ A,
              const float* __restrict__ X,
              const float* __restrict__ bias,
              float*       __restrict__ Cext)
{
    constexpr int K    = (MODE == 1) ? 128 : 256;
    constexpr int NC   = K / BK;
    constexpr int LDA  = (MODE == 2) ? 256 : LDA_W1;
    constexpr int COFF = (MODE == 1) ? 256 : 0;
    constexpr int LDX  = (MODE == 0) ? MPTS : NPTS;
    constexpr int XBS  = (MODE == 0) ? CH2 * MPTS : (MODE == 1) ? CH1 * NPTS : OUT1 * NPTS;

    __shared__ uint32_t As[2][128][ASTR];   // 20.0 KB
    __shared__ uint32_t Bs[2][BK][BSTR];    // 16.5 KB

    const int b     = blockIdx.z;
    const int nBase = blockIdx.x * BN;
    const int oBase = blockIdx.y * 128;
    const int tid   = threadIdx.x;
    const int wid   = tid >> 5;
    const int lane  = tid & 31;
    const int g     = lane >> 2;   // 0..7
    const int tc    = lane & 3;    // 0..3

    const int oW = (wid >> 2) * 64;   // 0 or 64
    const int nW = (wid & 3) * 64;    // 0,64,128,192

    const float* Xb = (MODE == 2) ? (g_y1 + (size_t)b * XBS) : (X + (size_t)b * XBS);

    // A: 128 rows x 8 k = 256 float4; one per thread.
    const int arow = tid & 127;
    const int ac4  = (tid >> 7) * 4;
    // B: 8 rows x 256 n = 512 float4; two per thread.
    const int bkr  = tid >> 6;          // 0..3 (and +4)
    const int bn4  = (tid & 63) * 4;    // 0..252

    float4 pa, pb0, pb1;

    auto load_chunk = [&](int c) {
        const int k0 = c * BK;
        pa  = *reinterpret_cast<const float4*>(
            &A[(size_t)(oBase + arow) * LDA + COFF + k0 + ac4]);
        pb0 = *reinterpret_cast<const float4*>(
            &Xb[(size_t)(k0 + bkr) * LDX + nBase + bn4]);
        pb1 = *reinterpret_cast<const float4*>(
            &Xb[(size_t)(k0 + bkr + 4) * LDX + nBase + bn4]);
    };
    auto store_chunk = [&](int buf) {
        uint4 ta = make_uint4(f2tf32(pa.x), f2tf32(pa.y), f2tf32(pa.z), f2tf32(pa.w));
        *reinterpret_cast<uint4*>(&As[buf][arow][ac4]) = ta;
        uint4 u0 = make_uint4(f2tf32(pb0.x), f2tf32(pb0.y), f2tf32(pb0.z), f2tf32(pb0.w));
        uint4 u1 = make_uint4(f2tf32(pb1.x), f2tf32(pb1.y), f2tf32(pb1.z), f2tf32(pb1.w));
        *reinterpret_cast<uint4*>(&Bs[buf][bkr    ][bn4]) = u0;
        *reinterpret_cast<uint4*>(&Bs[buf][bkr + 4][bn4]) = u1;
    };

    float c[4][8][4];   // [mi][ni][reg]  128 regs
    #pragma unroll
    for (int mi = 0; mi < 4; mi++)
        #pragma unroll
        for (int ni = 0; ni < 8; ni++)
            #pragma unroll
            for (int q = 0; q < 4; q++) c[mi][ni][q] = 0.0f;

    load_chunk(0);
    store_chunk(0);
    __syncthreads();

    for (int cc = 0; cc < NC; cc++) {
        const int cur = cc & 1;
        if (cc + 1 < NC) load_chunk(cc + 1);

        // ---- one 8-k step: 32 mma per warp ----
        uint32_t a[4][4];
        #pragma unroll
        for (int mi = 0; mi < 4; mi++) {
            int rb = oW + mi * 16;
            a[mi][0] = As[cur][rb + g    ][tc    ];
            a[mi][1] = As[cur][rb + g + 8][tc    ];
            a[mi][2] = As[cur][rb + g    ][tc + 4];
            a[mi][3] = As[cur][rb + g + 8][tc + 4];
        }
        uint32_t bb[8][2];
        #pragma unroll
        for (int ni = 0; ni < 8; ni++) {
            int nb = nW + ni * 8 + g;
            bb[ni][0] = Bs[cur][tc    ][nb];
            bb[ni][1] = Bs[cur][tc + 4][nb];
        }
        #pragma unroll
        for (int mi = 0; mi < 4; mi++)
            #pragma unroll
            for (int ni = 0; ni < 8; ni++) {
                asm volatile(
                    "mma.sync.aligned.m16n8k8.row.col.f32.tf32.tf32.f32 "
                    "{%0,%1,%2,%3}, {%4,%5,%6,%7}, {%8,%9}, {%0,%1,%2,%3};"
                    : "+f"(c[mi][ni][0]), "+f"(c[mi][ni][1]),
                      "+f"(c[mi][ni][2]), "+f"(c[mi][ni][3])
                    : "r"(a[mi][0]), "r"(a[mi][1]), "r"(a[mi][2]), "r"(a[mi][3]),
                      "r"(bb[ni][0]), "r"(bb[ni][1]));
            }

        if (cc + 1 < NC) {
            store_chunk((cc + 1) & 1);
            __syncthreads();
        }
    }

    // ---- epilogue ----
    // element (mi, ni, q): o = oBase+oW+mi*16+g+(q>=2)*8 ; n = nBase+nW+ni*8+tc*2+(q&1)

    if (MODE == 0) {
        // store transposed: Tt[m][o], o contiguous
        float* Cb = g_Tt + (size_t)b * MPTS * OUT1;
        #pragma unroll
        for (int ni = 0; ni < 8; ni++) {
            #pragma unroll
            for (int t = 0; t < 2; t++) {
                int m = nBase + nW + ni * 8 + tc * 2 + t;
                float* mrow = Cb + (size_t)m * OUT1;
                #pragma unroll
                for (int mi = 0; mi < 4; mi++) {
                    #pragma unroll
                    for (int h = 0; h < 2; h++) {
                        int o = oBase + oW + mi * 16 + g + h * 8;
                        mrow[o] = c[mi][ni][h * 2 + t];
                    }
                }
            }
        }
        return;
    }

    constexpr int LDC = NPTS;
    float* Cb = (MODE == 1) ? (g_y1 + (size_t)b * OUT1 * NPTS)
                            : (Cext + (size_t)b * OUT1 * NPTS);

    if (MODE == 1) {
        // gather from transposed T: rows contiguous in o
        const float* Tb = g_Tt + (size_t)b * MPTS * OUT1;
        const int*   ib = g_idx + (size_t)b * NPTS * 3;
        const float* wb = g_wgt + (size_t)b * NPTS * 3;
        #pragma unroll
        for (int ni = 0; ni < 8; ni++) {
            #pragma unroll
            for (int t = 0; t < 2; t++) {
                int n  = nBase + nW + ni * 8 + tc * 2 + t;
                int j0 = ib[n * 3 + 0], j1 = ib[n * 3 + 1], j2 = ib[n * 3 + 2];
                float w0 = wb[n * 3 + 0], w1 = wb[n * 3 + 1], w2 = wb[n * 3 + 2];
                const float* r0 = Tb + (size_t)j0 * OUT1;
                const float* r1 = Tb + (size_t)j1 * OUT1;
                const float* r2 = Tb + (size_t)j2 * OUT1;
                #pragma unroll
                for (int mi = 0; mi < 4; mi++) {
                    #pragma unroll
                    for (int h = 0; h < 2; h++) {
                        int o = oBase + oW + mi * 16 + g + h * 8;
                        c[mi][ni][h * 2 + t] +=
                            w0 * __ldg(&r0[o]) + w1 * __ldg(&r1[o]) + w2 * __ldg(&r2[o]);
                    }
                }
            }
        }
    }

    #pragma unroll
    for (int mi = 0; mi < 4; mi++) {
        #pragma unroll
        for (int h = 0; h < 2; h++) {
            int o = oBase + oW + mi * 16 + g + h * 8;
            float bv = bias[o];
            float* orow = Cb + (size_t)o * LDC;
            #pragma unroll
            for (int ni = 0; ni < 8; ni++) {
                int n = nBase + nW + ni * 8 + tc * 2;
                float v0 = fmaxf(c[mi][ni][h * 2 + 0] + bv, 0.0f);
                float v1 = fmaxf(c[mi][ni][h * 2 + 1] + bv, 0.0f);
                *reinterpret_cast<float2*>(&orow[n]) = make_float2(v0, v1);
            }
        }
    }
}

// ===========================================================================
extern "C" void kernel_launch(void* const* d_in, const int* in_sizes, int n_in,
                              void* d_out, int out_size)
{
    const float* xyz1    = (const float*)d_in[0];
    const float* xyz2    = (const float*)d_in[1];
    const float* points1 = (const float*)d_in[2];
    const float* points2 = (const float*)d_in[3];
    const float* W1      = (const float*)d_in[4];
    const float* b1      = (const float*)d_in[5];
    const float* W2      = (const float*)d_in[6];
    const float* b2      = (const float*)d_in[7];
    float*       out     = (float*)d_out;

    three_nn_kernel<<<dim3(NPTS / 256, NB), 256>>>(xyz1, xyz2);

    // Tt = (W1[:, :256] @ points2)^T
    gemm_mma<0><<<dim3(MPTS / BN, OUT1 / 128, NB), 256>>>(W1, points2, nullptr, nullptr);

    // y1 = relu(W1[:, 256:] @ points1 + b1 + gathered Tt)
    gemm_mma<1><<<dim3(NPTS / BN, OUT1 / 128, NB), 256>>>(W1, points1, b1, nullptr);

    // out = relu(W2 @ y1 + b2)
    gemm_mma<2><<<dim3(NPTS / BN, OUT2 / 128, NB), 256>>>(W2, nullptr, b2, out);
}

// round 6
// speedup vs baseline: 1.3020x; 1.3020x over previous
#include <cuda_runtime.h>
#include <math.h>
#include <cstdint>

// Problem constants
#define NB    16
#define NPTS  4096
#define MPTS  1024
#define CH2   256
#define CH1   128
#define OUT1  256
#define OUT2  256
#define LDA_W1 384

// ---- scratch ----
__device__ int   g_idx[NB * NPTS * 3];
__device__ float g_wgt[NB * NPTS * 3];
__device__ float g_Tt [NB * MPTS * OUT1];   // T transposed: [b][m][o], o contiguous
__device__ float g_y1 [NB * OUT1 * NPTS];   // layer-1 activations [b][k][n]

// ===========================================================================
// Kernel 1: three_nn + weights
// ===========================================================================
__global__ __launch_bounds__(256)
void three_nn_kernel(const float* __restrict__ xyz1, const float* __restrict__ xyz2)
{
    __shared__ float sx[MPTS], sy[MPTS], sz[MPTS], ss[MPTS];
    const int b = blockIdx.y;
    const float* x2 = xyz2 + (size_t)b * 3 * MPTS;
    for (int i = threadIdx.x; i < MPTS; i += blockDim.x) {
        float xv = x2[i], yv = x2[MPTS + i], zv = x2[2 * MPTS + i];
        sx[i] = xv; sy[i] = yv; sz[i] = zv;
        ss[i] = xv * xv + yv * yv + zv * zv;
    }
    __syncthreads();

    const int n = blockIdx.x * blockDim.x + threadIdx.x;
    const float* x1 = xyz1 + (size_t)b * 3 * NPTS;
    const float px = x1[n], py = x1[NPTS + n], pz = x1[2 * NPTS + n];
    const float sq1 = px * px + py * py + pz * pz;

    float d0 = 1e30f, d1 = 1e30f, d2 = 1e30f;
    int   i0 = 0, i1 = 0, i2 = 0;

    #pragma unroll 4
    for (int m = 0; m < MPTS; m++) {
        float inner = fmaf(px, sx[m], fmaf(py, sy[m], pz * sz[m]));
        float d = fmaf(-2.0f, inner, sq1 + ss[m]);
        if (d < d2) {
            if (d < d1) {
                d2 = d1; i2 = i1;
                if (d < d0) { d1 = d0; i1 = i0; d0 = d; i0 = m; }
                else        { d1 = d;  i1 = m; }
            } else { d2 = d; i2 = m; }
        }
    }

    float r0 = 1.0f / fmaxf(sqrtf(fmaxf(d0, 1e-20f)), 1e-10f);
    float r1 = 1.0f / fmaxf(sqrtf(fmaxf(d1, 1e-20f)), 1e-10f);
    float r2 = 1.0f / fmaxf(sqrtf(fmaxf(d2, 1e-20f)), 1e-10f);
    float inv = 1.0f / (r0 + r1 + r2);

    const int base = (b * NPTS + n) * 3;
    g_idx[base + 0] = i0; g_idx[base + 1] = i1; g_idx[base + 2] = i2;
    g_wgt[base + 0] = r0 * inv; g_wgt[base + 1] = r1 * inv; g_wgt[base + 2] = r2 * inv;
}

// ===========================================================================
// tf32 mma.sync GEMM, cp.async double-buffered, CTA 128x128, warp 64x32, BK=16.
//   MODE 0: Tt  = (W1[:, :256] @ points2)^T                 -> g_Tt [m][o]
//   MODE 1: y1  = relu(W1[:,256:] @ points1 + b1 + gather)  -> g_y1
//   MODE 2: out = relu(W2 @ y1 + b2)                        -> d_out
// smem holds raw f32; cvt.rna.tf32 applied after LDS (numerics == R4).
// ===========================================================================
__device__ __forceinline__ uint32_t f2tf32(float x) {
    uint32_t r;
    asm("cvt.rna.tf32.f32 %0, %1;" : "=r"(r) : "f"(x));
    return r;
}
__device__ __forceinline__ uint32_t smem_u32(const void* p) {
    uint32_t a;
    asm("{ .reg .u64 t; cvta.to.shared.u64 t, %1; cvt.u32.u64 %0, t; }" : "=r"(a) : "l"(p));
    return a;
}
__device__ __forceinline__ void cp16(void* dst, const void* src) {
    asm volatile("cp.async.ca.shared.global [%0], [%1], 16;"
                 :: "r"(smem_u32(dst)), "l"(src));
}

#define BK     16
#define ASTR   20    // frag bank = (20g+tc)%32 = 4g+tc bijective
#define BSTR   136   // (128+8): frag bank = (8k+n)%32 bijective

template <int MODE>
__global__ __launch_bounds__(256)
void gemm_mma(const float* __restrict__ A,
              const float* __restrict__ X,
              const float* __restrict__ bias,
              float*       __restrict__ Cext)
{
    constexpr int K    = (MODE == 1) ? 128 : 256;
    constexpr int NC   = K / BK;
    constexpr int LDA  = (MODE == 2) ? 256 : LDA_W1;
    constexpr int COFF = (MODE == 1) ? 256 : 0;
    constexpr int LDX  = (MODE == 0) ? MPTS : NPTS;
    constexpr int XBS  = (MODE == 0) ? CH2 * MPTS : (MODE == 1) ? CH1 * NPTS : OUT1 * NPTS;

    __shared__ float As[2][128][ASTR];   // 20.0 KB
    __shared__ float Bs[2][BK][BSTR];    // 17.4 KB

    const int b     = blockIdx.z;
    const int nBase = blockIdx.x * 128;
    const int oBase = blockIdx.y * 128;
    const int tid   = threadIdx.x;
    const int wid   = tid >> 5;
    const int lane  = tid & 31;
    const int g     = lane >> 2;   // 0..7
    const int tc    = lane & 3;    // 0..3

    const int oW = (wid >> 2) * 64;
    const int nW = (wid & 3) * 32;

    const float* Xb = (MODE == 2) ? (g_y1 + (size_t)b * XBS) : (X + (size_t)b * XBS);

    // A: 128 rows x 16 k: thread does rows (arow0, arow0+64), 4 k each.
    const int arow0 = tid >> 2;          // 0..63
    const int ac4   = (tid & 3) * 4;     // 0,4,8,12
    // B: 16 rows x 128 n: thread does rows (bkr0, bkr0+8), 4 n each.
    const int bkr0  = tid >> 5;          // 0..7
    const int bc4   = (tid & 31) * 4;    // 0..124

    auto prefetch = [&](int c) {
        const int buf = c & 1;
        const int k0  = c * BK;
        const float* ap = &A[(size_t)(oBase + arow0) * LDA + COFF + k0 + ac4];
        cp16(&As[buf][arow0     ][ac4], ap);
        cp16(&As[buf][arow0 + 64][ac4], ap + (size_t)64 * LDA);
        const float* bp = &Xb[(size_t)(k0 + bkr0) * LDX + nBase + bc4];
        cp16(&Bs[buf][bkr0    ][bc4], bp);
        cp16(&Bs[buf][bkr0 + 8][bc4], bp + (size_t)8 * LDX);
        asm volatile("cp.async.commit_group;" ::: "memory");
    };

    float c[4][4][4];   // [mi][ni][reg]
    #pragma unroll
    for (int mi = 0; mi < 4; mi++)
        #pragma unroll
        for (int ni = 0; ni < 4; ni++)
            #pragma unroll
            for (int q = 0; q < 4; q++) c[mi][ni][q] = 0.0f;

    prefetch(0);
    asm volatile("cp.async.wait_group 0;" ::: "memory");
    __syncthreads();

    for (int cc = 0; cc < NC; cc++) {
        const int cur = cc & 1;
        if (cc + 1 < NC) prefetch(cc + 1);

        #pragma unroll
        for (int kk = 0; kk < BK; kk += 8) {
            uint32_t a[4][4];
            #pragma unroll
            for (int mi = 0; mi < 4; mi++) {
                int rb = oW + mi * 16;
                a[mi][0] = f2tf32(As[cur][rb + g    ][kk + tc    ]);
                a[mi][1] = f2tf32(As[cur][rb + g + 8][kk + tc    ]);
                a[mi][2] = f2tf32(As[cur][rb + g    ][kk + tc + 4]);
                a[mi][3] = f2tf32(As[cur][rb + g + 8][kk + tc + 4]);
            }
            uint32_t bb[4][2];
            #pragma unroll
            for (int ni = 0; ni < 4; ni++) {
                int nb = nW + ni * 8 + g;
                bb[ni][0] = f2tf32(Bs[cur][kk + tc    ][nb]);
                bb[ni][1] = f2tf32(Bs[cur][kk + tc + 4][nb]);
            }
            #pragma unroll
            for (int mi = 0; mi < 4; mi++)
                #pragma unroll
                for (int ni = 0; ni < 4; ni++) {
                    asm volatile(
                        "mma.sync.aligned.m16n8k8.row.col.f32.tf32.tf32.f32 "
                        "{%0,%1,%2,%3}, {%4,%5,%6,%7}, {%8,%9}, {%0,%1,%2,%3};"
                        : "+f"(c[mi][ni][0]), "+f"(c[mi][ni][1]),
                          "+f"(c[mi][ni][2]), "+f"(c[mi][ni][3])
                        : "r"(a[mi][0]), "r"(a[mi][1]), "r"(a[mi][2]), "r"(a[mi][3]),
                          "r"(bb[ni][0]), "r"(bb[ni][1]));
                }
        }

        asm volatile("cp.async.wait_group 0;" ::: "memory");
        __syncthreads();
    }

    // ---- epilogue ----
    // element (mi, ni, q): o = oBase+oW+mi*16+g+(q>=2)*8 ; n = nBase+nW+ni*8+tc*2+(q&1)

    if (MODE == 0) {
        // store transposed: Tt[m][o], o contiguous
        float* Cb = g_Tt + (size_t)b * MPTS * OUT1;
        #pragma unroll
        for (int ni = 0; ni < 4; ni++) {
            #pragma unroll
            for (int t = 0; t < 2; t++) {
                int m = nBase + nW + ni * 8 + tc * 2 + t;
                float* mrow = Cb + (size_t)m * OUT1;
                #pragma unroll
                for (int mi = 0; mi < 4; mi++) {
                    #pragma unroll
                    for (int h = 0; h < 2; h++) {
                        int o = oBase + oW + mi * 16 + g + h * 8;
                        mrow[o] = c[mi][ni][h * 2 + t];
                    }
                }
            }
        }
        return;
    }

    constexpr int LDC = NPTS;
    float* Cb = (MODE == 1) ? (g_y1 + (size_t)b * OUT1 * NPTS)
                            : (Cext + (size_t)b * OUT1 * NPTS);

    if (MODE == 1) {
        // gather from transposed T: rows contiguous in o
        const float* Tb = g_Tt + (size_t)b * MPTS * OUT1;
        const int*   ib = g_idx + (size_t)b * NPTS * 3;
        const float* wb = g_wgt + (size_t)b * NPTS * 3;
        #pragma unroll
        for (int ni = 0; ni < 4; ni++) {
            #pragma unroll
            for (int t = 0; t < 2; t++) {
                int n  = nBase + nW + ni * 8 + tc * 2 + t;
                int j0 = ib[n * 3 + 0], j1 = ib[n * 3 + 1], j2 = ib[n * 3 + 2];
                float w0 = wb[n * 3 + 0], w1 = wb[n * 3 + 1], w2 = wb[n * 3 + 2];
                const float* r0 = Tb + (size_t)j0 * OUT1;
                const float* r1 = Tb + (size_t)j1 * OUT1;
                const float* r2 = Tb + (size_t)j2 * OUT1;
                #pragma unroll
                for (int mi = 0; mi < 4; mi++) {
                    #pragma unroll
                    for (int h = 0; h < 2; h++) {
                        int o = oBase + oW + mi * 16 + g + h * 8;
                        c[mi][ni][h * 2 + t] +=
                            w0 * __ldg(&r0[o]) + w1 * __ldg(&r1[o]) + w2 * __ldg(&r2[o]);
                    }
                }
            }
        }
    }

    #pragma unroll
    for (int mi = 0; mi < 4; mi++) {
        #pragma unroll
        for (int h = 0; h < 2; h++) {
            int o = oBase + oW + mi * 16 + g + h * 8;
            float bv = bias[o];
            float* orow = Cb + (size_t)o * LDC;
            #pragma unroll
            for (int ni = 0; ni < 4; ni++) {
                int n = nBase + nW + ni * 8 + tc * 2;
                float v0 = fmaxf(c[mi][ni][h * 2 + 0] + bv, 0.0f);
                float v1 = fmaxf(c[mi][ni][h * 2 + 1] + bv, 0.0f);
                *reinterpret_cast<float2*>(&orow[n]) = make_float2(v0, v1);
            }
        }
    }
}

// ===========================================================================
extern "C" void kernel_launch(void* const* d_in, const int* in_sizes, int n_in,
                              void* d_out, int out_size)
{
    const float* xyz1    = (const float*)d_in[0];
    const float* xyz2    = (const float*)d_in[1];
    const float* points1 = (const float*)d_in[2];
    const float* points2 = (const float*)d_in[3];
    const float* W1      = (const float*)d_in[4];
    const float* b1      = (const float*)d_in[5];
    const float* W2      = (const float*)d_in[6];
    const float* b2      = (const float*)d_in[7];
    float*       out     = (float*)d_out;

    three_nn_kernel<<<dim3(NPTS / 256, NB), 256>>>(xyz1, xyz2);

    // Tt = (W1[:, :256] @ points2)^T
    gemm_mma<0><<<dim3(MPTS / 128, OUT1 / 128, NB), 256>>>(W1, points2, nullptr, nullptr);

    // y1 = relu(W1[:, 256:] @ points1 + b1 + gathered Tt)
    gemm_mma<1><<<dim3(NPTS / 128, OUT1 / 128, NB), 256>>>(W1, points1, b1, nullptr);

    // out = relu(W2 @ y1 + b2)
    gemm_mma<2><<<dim3(NPTS / 128, OUT2 / 128, NB), 256>>>(W2, nullptr, b2, out);
}

// round 7
// speedup vs baseline: 1.3174x; 1.0118x over previous
#include <cuda_runtime.h>
#include <math.h>
#include <cstdint>

// Problem constants
#define NB    16
#define NPTS  4096
#define MPTS  1024
#define CH2   256
#define CH1   128
#define OUT1  256
#define OUT2  256
#define LDA_W1 384

// ---- scratch ----
__device__ int   g_idx[NB * NPTS * 3];
__device__ float g_wgt[NB * NPTS * 3];
__device__ float g_Tt [NB * MPTS * OUT1];   // T transposed: [b][m][o], o contiguous
__device__ float g_y1 [NB * OUT1 * NPTS];   // layer-1 activations [b][k][n]

// ===========================================================================
// Kernel 1: three_nn + weights
// ===========================================================================
__global__ __launch_bounds__(256)
void three_nn_kernel(const float* __restrict__ xyz1, const float* __restrict__ xyz2)
{
    __shared__ float sx[MPTS], sy[MPTS], sz[MPTS], ss[MPTS];
    const int b = blockIdx.y;
    const float* x2 = xyz2 + (size_t)b * 3 * MPTS;
    for (int i = threadIdx.x; i < MPTS; i += blockDim.x) {
        float xv = x2[i], yv = x2[MPTS + i], zv = x2[2 * MPTS + i];
        sx[i] = xv; sy[i] = yv; sz[i] = zv;
        ss[i] = xv * xv + yv * yv + zv * zv;
    }
    __syncthreads();

    const int n = blockIdx.x * blockDim.x + threadIdx.x;
    const float* x1 = xyz1 + (size_t)b * 3 * NPTS;
    const float px = x1[n], py = x1[NPTS + n], pz = x1[2 * NPTS + n];
    const float sq1 = px * px + py * py + pz * pz;

    float d0 = 1e30f, d1 = 1e30f, d2 = 1e30f;
    int   i0 = 0, i1 = 0, i2 = 0;

    #pragma unroll 4
    for (int m = 0; m < MPTS; m++) {
        float inner = fmaf(px, sx[m], fmaf(py, sy[m], pz * sz[m]));
        float d = fmaf(-2.0f, inner, sq1 + ss[m]);
        if (d < d2) {
            if (d < d1) {
                d2 = d1; i2 = i1;
                if (d < d0) { d1 = d0; i1 = i0; d0 = d; i0 = m; }
                else        { d1 = d;  i1 = m; }
            } else { d2 = d; i2 = m; }
        }
    }

    float r0 = 1.0f / fmaxf(sqrtf(fmaxf(d0, 1e-20f)), 1e-10f);
    float r1 = 1.0f / fmaxf(sqrtf(fmaxf(d1, 1e-20f)), 1e-10f);
    float r2 = 1.0f / fmaxf(sqrtf(fmaxf(d2, 1e-20f)), 1e-10f);
    float inv = 1.0f / (r0 + r1 + r2);

    const int base = (b * NPTS + n) * 3;
    g_idx[base + 0] = i0; g_idx[base + 1] = i1; g_idx[base + 2] = i2;
    g_wgt[base + 0] = r0 * inv; g_wgt[base + 1] = r1 * inv; g_wgt[base + 2] = r2 * inv;
}

// ===========================================================================
// tf32 mma.sync GEMM. 128-thread CTAs (4 warps, 2x2), CTA tile 128(o) x 64(n),
// warp tile 64x32, BK=16, cp.async double buffer, 5 CTAs/SM target.
//   MODE 0: Tt  = (W1[:, :256] @ points2)^T                 -> g_Tt [m][o]
//   MODE 1: y1  = relu(W1[:,256:] @ points1 + b1 + gather)  -> g_y1
//   MODE 2: out = relu(W2 @ y1 + b2)                        -> d_out
// ===========================================================================
__device__ __forceinline__ uint32_t f2tf32(float x) {
    uint32_t r;
    asm("cvt.rna.tf32.f32 %0, %1;" : "=r"(r) : "f"(x));
    return r;
}
__device__ __forceinline__ uint32_t smem_u32(const void* p) {
    uint32_t a;
    asm("{ .reg .u64 t; cvta.to.shared.u64 t, %1; cvt.u32.u64 %0, t; }" : "=r"(a) : "l"(p));
    return a;
}
__device__ __forceinline__ void cp16(void* dst, const void* src) {
    asm volatile("cp.async.ca.shared.global [%0], [%1], 16;"
                 :: "r"(smem_u32(dst)), "l"(src));
}

#define BK     16
#define BN     64
#define ASTR   20    // frag bank = (20g+tc)%32 = 4g+tc bijective
#define BSTR   72    // (64+8): frag bank = (8k+n)%32 bijective

template <int MODE>
__global__ __launch_bounds__(128, 5)
void gemm_mma(const float* __restrict__ A,
              const float* __restrict__ X,
              const float* __restrict__ bias,
              float*       __restrict__ Cext)
{
    constexpr int K    = (MODE == 1) ? 128 : 256;
    constexpr int NC   = K / BK;
    constexpr int LDA  = (MODE == 2) ? 256 : LDA_W1;
    constexpr int COFF = (MODE == 1) ? 256 : 0;
    constexpr int LDX  = (MODE == 0) ? MPTS : NPTS;
    constexpr int XBS  = (MODE == 0) ? CH2 * MPTS : (MODE == 1) ? CH1 * NPTS : OUT1 * NPTS;

    __shared__ float As[2][128][ASTR];   // 20.0 KB
    __shared__ float Bs[2][BK][BSTR];    // 9.0 KB

    const int b     = blockIdx.z;
    const int nBase = blockIdx.x * BN;
    const int oBase = blockIdx.y * 128;
    const int tid   = threadIdx.x;
    const int wid   = tid >> 5;
    const int lane  = tid & 31;
    const int g     = lane >> 2;   // 0..7
    const int tc    = lane & 3;    // 0..3

    const int oW = (wid >> 1) * 64;   // 0 or 64
    const int nW = (wid & 1) * 32;    // 0 or 32

    const float* Xb = (MODE == 2) ? (g_y1 + (size_t)b * XBS) : (X + (size_t)b * XBS);

    // A tile 128 x 16: 512 float4, 4 per thread (rows arow0 + {0,32,64,96})
    const int arow0 = tid >> 2;          // 0..31
    const int ac4   = (tid & 3) * 4;     // 0,4,8,12
    // B tile 16 x 64: 256 float4, 2 per thread (rows bkr0, bkr0+8)
    const int bkr0  = tid >> 4;          // 0..7
    const int bc4   = (tid & 15) * 4;    // 0..60

    auto prefetch = [&](int c) {
        const int buf = c & 1;
        const int k0  = c * BK;
        const float* ap = &A[(size_t)(oBase + arow0) * LDA + COFF + k0 + ac4];
        cp16(&As[buf][arow0     ][ac4], ap);
        cp16(&As[buf][arow0 + 32][ac4], ap + (size_t)32 * LDA);
        cp16(&As[buf][arow0 + 64][ac4], ap + (size_t)64 * LDA);
        cp16(&As[buf][arow0 + 96][ac4], ap + (size_t)96 * LDA);
        const float* bp = &Xb[(size_t)(k0 + bkr0) * LDX + nBase + bc4];
        cp16(&Bs[buf][bkr0    ][bc4], bp);
        cp16(&Bs[buf][bkr0 + 8][bc4], bp + (size_t)8 * LDX);
        asm volatile("cp.async.commit_group;" ::: "memory");
    };

    float c[4][4][4];   // [mi][ni][reg]
    #pragma unroll
    for (int mi = 0; mi < 4; mi++)
        #pragma unroll
        for (int ni = 0; ni < 4; ni++)
            #pragma unroll
            for (int q = 0; q < 4; q++) c[mi][ni][q] = 0.0f;

    prefetch(0);
    asm volatile("cp.async.wait_group 0;" ::: "memory");
    __syncthreads();

    for (int cc = 0; cc < NC; cc++) {
        const int cur = cc & 1;
        if (cc + 1 < NC) prefetch(cc + 1);

        #pragma unroll
        for (int kk = 0; kk < BK; kk += 8) {
            uint32_t a[4][4];
            #pragma unroll
            for (int mi = 0; mi < 4; mi++) {
                int rb = oW + mi * 16;
                a[mi][0] = f2tf32(As[cur][rb + g    ][kk + tc    ]);
                a[mi][1] = f2tf32(As[cur][rb + g + 8][kk + tc    ]);
                a[mi][2] = f2tf32(As[cur][rb + g    ][kk + tc + 4]);
                a[mi][3] = f2tf32(As[cur][rb + g + 8][kk + tc + 4]);
            }
            uint32_t bb[4][2];
            #pragma unroll
            for (int ni = 0; ni < 4; ni++) {
                int nb = nW + ni * 8 + g;
                bb[ni][0] = f2tf32(Bs[cur][kk + tc    ][nb]);
                bb[ni][1] = f2tf32(Bs[cur][kk + tc + 4][nb]);
            }
            #pragma unroll
            for (int mi = 0; mi < 4; mi++)
                #pragma unroll
                for (int ni = 0; ni < 4; ni++) {
                    asm volatile(
                        "mma.sync.aligned.m16n8k8.row.col.f32.tf32.tf32.f32 "
                        "{%0,%1,%2,%3}, {%4,%5,%6,%7}, {%8,%9}, {%0,%1,%2,%3};"
                        : "+f"(c[mi][ni][0]), "+f"(c[mi][ni][1]),
                          "+f"(c[mi][ni][2]), "+f"(c[mi][ni][3])
                        : "r"(a[mi][0]), "r"(a[mi][1]), "r"(a[mi][2]), "r"(a[mi][3]),
                          "r"(bb[ni][0]), "r"(bb[ni][1]));
                }
        }

        asm volatile("cp.async.wait_group 0;" ::: "memory");
        __syncthreads();
    }

    // ---- epilogue ----
    // element (mi, ni, q): o = oBase+oW+mi*16+g+(q>=2)*8 ; n = nBase+nW+ni*8+tc*2+(q&1)

    if (MODE == 0) {
        // store transposed: Tt[m][o], o contiguous
        float* Cb = g_Tt + (size_t)b * MPTS * OUT1;
        #pragma unroll
        for (int ni = 0; ni < 4; ni++) {
            #pragma unroll
            for (int t = 0; t < 2; t++) {
                int m = nBase + nW + ni * 8 + tc * 2 + t;
                float* mrow = Cb + (size_t)m * OUT1;
                #pragma unroll
                for (int mi = 0; mi < 4; mi++) {
                    #pragma unroll
                    for (int h = 0; h < 2; h++) {
                        int o = oBase + oW + mi * 16 + g + h * 8;
                        mrow[o] = c[mi][ni][h * 2 + t];
                    }
                }
            }
        }
        return;
    }

    constexpr int LDC = NPTS;
    float* Cb = (MODE == 1) ? (g_y1 + (size_t)b * OUT1 * NPTS)
                            : (Cext + (size_t)b * OUT1 * NPTS);

    if (MODE == 1) {
        // gather from transposed T: rows contiguous in o
        const float* Tb = g_Tt + (size_t)b * MPTS * OUT1;
        const int*   ib = g_idx + (size_t)b * NPTS * 3;
        const float* wb = g_wgt + (size_t)b * NPTS * 3;
        #pragma unroll
        for (int ni = 0; ni < 4; ni++) {
            #pragma unroll
            for (int t = 0; t < 2; t++) {
                int n  = nBase + nW + ni * 8 + tc * 2 + t;
                int j0 = ib[n * 3 + 0], j1 = ib[n * 3 + 1], j2 = ib[n * 3 + 2];
                float w0 = wb[n * 3 + 0], w1 = wb[n * 3 + 1], w2 = wb[n * 3 + 2];
                const float* r0 = Tb + (size_t)j0 * OUT1;
                const float* r1 = Tb + (size_t)j1 * OUT1;
                const float* r2 = Tb + (size_t)j2 * OUT1;
                #pragma unroll
                for (int mi = 0; mi < 4; mi++) {
                    #pragma unroll
                    for (int h = 0; h < 2; h++) {
                        int o = oBase + oW + mi * 16 + g + h * 8;
                        c[mi][ni][h * 2 + t] +=
                            w0 * __ldg(&r0[o]) + w1 * __ldg(&r1[o]) + w2 * __ldg(&r2[o]);
                    }
                }
            }
        }
    }

    #pragma unroll
    for (int mi = 0; mi < 4; mi++) {
        #pragma unroll
        for (int h = 0; h < 2; h++) {
            int o = oBase + oW + mi * 16 + g + h * 8;
            float bv = bias[o];
            float* orow = Cb + (size_t)o * LDC;
            #pragma unroll
            for (int ni = 0; ni < 4; ni++) {
                int n = nBase + nW + ni * 8 + tc * 2;
                float v0 = fmaxf(c[mi][ni][h * 2 + 0] + bv, 0.0f);
                float v1 = fmaxf(c[mi][ni][h * 2 + 1] + bv, 0.0f);
                *reinterpret_cast<float2*>(&orow[n]) = make_float2(v0, v1);
            }
        }
    }
}

// ===========================================================================
extern "C" void kernel_launch(void* const* d_in, const int* in_sizes, int n_in,
                              void* d_out, int out_size)
{
    const float* xyz1    = (const float*)d_in[0];
    const float* xyz2    = (const float*)d_in[1];
    const float* points1 = (const float*)d_in[2];
    const float* points2 = (const float*)d_in[3];
    const float* W1      = (const float*)d_in[4];
    const float* b1      = (const float*)d_in[5];
    const float* W2      = (const float*)d_in[6];
    const float* b2      = (const float*)d_in[7];
    float*       out     = (float*)d_out;

    three_nn_kernel<<<dim3(NPTS / 256, NB), 256>>>(xyz1, xyz2);

    // Tt = (W1[:, :256] @ points2)^T
    gemm_mma<0><<<dim3(MPTS / BN, OUT1 / 128, NB), 128>>>(W1, points2, nullptr, nullptr);

    // y1 = relu(W1[:, 256:] @ points1 + b1 + gathered Tt)
    gemm_mma<1><<<dim3(NPTS / BN, OUT1 / 128, NB), 128>>>(W1, points1, b1, nullptr);

    // out = relu(W2 @ y1 + b2)
    gemm_mma<2><<<dim3(NPTS / BN, OUT2 / 128, NB), 128>>>(W2, nullptr, b2, out);
}